// round 13
// baseline (speedup 1.0000x reference)
#include <cuda_runtime.h>

#define Nn   128
#define Hh   2
#define Ll   1024
#define Cc   (Hh * Ll)      /* 2048 columns = h*L flattened */
#define PRED (Nn * Cc)      /* 262144 */
#define NB   128            /* grid size (one wave, all co-resident) */

#define ALD  132            /* smem lead dim (conflict-free fragment reads) */
/* smem u32 words: sA_raw[128*ALD] sBhi[16*ALD] */
#define SMEM_U32   (144 * ALD)
#define SMEM_BYTES (SMEM_U32 * 4)   /* 76032 */

__device__ float    g_alpha[PRED];
__device__ float    g_Ss[PRED];
__device__ unsigned g_arrive;       /* monotonic grid-barrier ticket counter */

// ---- helpers ---------------------------------------------------------------
__device__ __forceinline__ unsigned f2tf32(float f) {
    unsigned u;
    asm("cvt.rna.tf32.f32 %0, %1;" : "=r"(u) : "f"(f));
    return u;
}
__device__ __forceinline__ void mma_tf32(float& d0, float& d1, float& d2, float& d3,
                                         unsigned a0, unsigned a1, unsigned a2, unsigned a3,
                                         unsigned b0, unsigned b1) {
    asm("mma.sync.aligned.m16n8k8.row.col.f32.tf32.tf32.f32 "
        "{%0,%1,%2,%3}, {%4,%5,%6,%7}, {%8,%9}, {%0,%1,%2,%3};"
        : "+f"(d0), "+f"(d1), "+f"(d2), "+f"(d3)
        : "r"(a0), "r"(a1), "r"(a2), "r"(a3), "r"(b0), "r"(b1));
}
__device__ __forceinline__ void cp_async16(unsigned smem_addr, const void* gptr) {
    asm volatile("cp.async.cg.shared.global [%0], [%1], 16;"
                 :: "r"(smem_addr), "l"(gptr) : "memory");
}

// Replay-safe grid barrier (monotonic ticket; no reset across graph replays).
__device__ __forceinline__ void grid_sync() {
    __syncthreads();
    if (threadIdx.x == 0) {
        __threadfence();
        unsigned t = atomicAdd(&g_arrive, 1u);
        unsigned target = (t / NB + 1u) * NB;
        unsigned v;
        do {
            asm volatile("ld.acquire.gpu.u32 %0, [%1];" : "=r"(v) : "l"(&g_arrive));
            if (v < target) __nanosleep(32);
        } while (v < target);
    }
    __syncthreads();
}

// ---------------------------------------------------------------------------
// Fused kernel: phase A scan (+A prefetch via cp.async) -> grid barrier ->
// phase B tensor-core GEMM (single-tf32) with fused epilogue.
// Grid 128 x 256 threads. Block b: scan rows 2b,2b+1; GEMM cols b*16..+15.
// __launch_bounds__(256, 1): prevent the regs=32 clamp (R12 spilled locals).
// ---------------------------------------------------------------------------
__global__ void __launch_bounds__(256, 1) fused_kernel(const float* __restrict__ x,
                                                       const float* __restrict__ Amat,
                                                       const float* __restrict__ taus,
                                                       const float* __restrict__ r0dt,
                                                       float* __restrict__ out)
{
    extern __shared__ unsigned sm_u[];
    float*    sA   = reinterpret_cast<float*>(sm_u);      // [128][ALD] raw fp32 Amat
    unsigned* sBhi = sm_u + 128 * ALD;                    // [16][ALD]  ([n][k=m]) tf32
    __shared__ float wI[8], wC[8];

    int tid = threadIdx.x;
    int b   = blockIdx.x;
    unsigned sbase = (unsigned)__cvta_generic_to_shared(sm_u);

    // ---- A prefetch: full 128x128 Amat -> smem (overlaps entire phase A) ---
#pragma unroll
    for (int j = 0; j < 16; j++) {
        int i = j * 256 + tid;
        int r = i >> 5, cq = (i & 31) * 4;
        cp_async16(sbase + (unsigned)(r * ALD + cq) * 4, &Amat[r * 128 + cq]);
    }
    asm volatile("cp.async.commit_group;" ::: "memory");

    // ---- Phase A: scan rows 2b (threads 0-127) and 2b+1 (threads 128-255) --
    int half = tid >> 7;            // 0 or 1
    int t    = tid & 127;
    int row  = 2 * b + half;
    int lane = tid & 31;
    int wloc = (tid >> 5) & 3;      // warp index within this half
    int base = row * Ll + t * 8;

    const float4* xv = reinterpret_cast<const float4*>(x + base);
    float4 v0 = xv[0], v1 = xv[1];
    float s[8] = { fmaxf(v0.x, 0.f), fmaxf(v0.y, 0.f), fmaxf(v0.z, 0.f), fmaxf(v0.w, 0.f),
                   fmaxf(v1.x, 0.f), fmaxf(v1.y, 0.f), fmaxf(v1.z, 0.f), fmaxf(v1.w, 0.f) };

    // third output: tempAmat.T = Amat + I (block b handles row b)
    if (tid < 128) {
        float a = Amat[b * 128 + tid];
        out[2 * PRED + b * 128 + tid] = a + (b == tid ? 1.f : 0.f);
    }

    float tau = taus[row];
    float R0  = r0dt[row];
    float d   = 1.f - 1.f / tau;

    float cum = 0.f, isv = 0.f;
#pragma unroll
    for (int k = 0; k < 8; k++) { cum += s[k]; isv = fmaf(d, isv, s[k]); }

    float d2 = d * d, d4 = d2 * d2, r8 = d4 * d4;   // d^8

    float inclI = isv, inclC = cum, rp = r8;
#pragma unroll
    for (int off = 1; off < 32; off <<= 1) {
        float ui = __shfl_up_sync(0xffffffffu, inclI, off);
        float uc = __shfl_up_sync(0xffffffffu, inclC, off);
        if (lane >= off) { inclI = fmaf(rp, ui, inclI); inclC += uc; }
        rp *= rp;
    }

    if (lane == 31) { wI[half * 4 + wloc] = inclI; wC[half * 4 + wloc] = inclC; }
    __syncthreads();

    float Rw = rp;                                  // d^256
    float exI = 0.f, exC = 0.f, aI = 0.f, aC = 0.f;
#pragma unroll
    for (int w = 0; w < 4; w++) {
        if (w == wloc) { exI = aI; exC = aC; }
        aI = fmaf(Rw, aI, wI[half * 4 + w]);
        aC += wC[half * 4 + w];
    }

    float upI = __shfl_up_sync(0xffffffffu, inclI, 1);
    float upC = __shfl_up_sync(0xffffffffu, inclC, 1);
    if (lane == 0) { upI = 0.f; upC = 0.f; }
    float XI = fmaf(exI, __powf(r8, (float)lane), upI);
    float XC = upC + exC;

    float al[8], ss[8];
    float ci = XI, cc = XC;
#pragma unroll
    for (int k = 0; k < 8; k++) {
        ci = fmaf(d, ci, s[k]);
        cc += s[k];
        al[k] = 1.f - __expf(-R0 * ci);
        ss[k] = 1.f - cc;
    }

    float4* ga = reinterpret_cast<float4*>(g_alpha + base);
    ga[0] = make_float4(al[0], al[1], al[2], al[3]);
    ga[1] = make_float4(al[4], al[5], al[6], al[7]);
    float4* gs = reinterpret_cast<float4*>(g_Ss + base);
    gs[0] = make_float4(ss[0], ss[1], ss[2], ss[3]);
    gs[1] = make_float4(ss[4], ss[5], ss[6], ss[7]);
    float4* go = reinterpret_cast<float4*>(out + PRED + base);   // signal output
    go[0] = make_float4(s[0], s[1], s[2], s[3]);
    go[1] = make_float4(s[4], s[5], s[6], s[7]);

    // A must be in smem before phase B; all alpha must be globally visible.
    asm volatile("cp.async.wait_group 0;" ::: "memory");
    grid_sync();

    // ---- Phase B: B-tile fill (L2-hot alpha -> tf32, transposed) -----------
    int c0 = b * 16;
    {
        int m  = tid >> 1;
        int j0 = (tid & 1) * 8;
        const float4* src = reinterpret_cast<const float4*>(&g_alpha[m * Cc + c0 + j0]);
        float4 q0 = src[0], q1 = src[1];
        float v[8] = { q0.x, q0.y, q0.z, q0.w, q1.x, q1.y, q1.z, q1.w };
#pragma unroll
        for (int j = 0; j < 8; j++)
            sBhi[(j0 + j) * ALD + m] = f2tf32(v[j]);
    }

    // ---- Hoist epilogue operands (L2-hot) so the mainloop hides their latency
    int wy = tid >> 5;               // warp 0..7
    int qr = lane >> 2;              // 0..7
    int qc = lane & 3;               // 0..3
    float2 alv[2][2], ssv[2][2];
#pragma unroll
    for (int nt = 0; nt < 2; nt++) {
        int gc  = c0 + nt * 8 + 2 * qc;
        int rr0 = wy * 16 + qr;
        int rr1 = rr0 + 8;
        alv[nt][0] = *reinterpret_cast<const float2*>(&g_alpha[rr0 * Cc + gc]);
        ssv[nt][0] = *reinterpret_cast<const float2*>(&g_Ss[rr0 * Cc + gc]);
        alv[nt][1] = *reinterpret_cast<const float2*>(&g_alpha[rr1 * Cc + gc]);
        ssv[nt][1] = *reinterpret_cast<const float2*>(&g_Ss[rr1 * Cc + gc]);
    }
    __syncthreads();

    // ---- GEMM mainloop: 8 warps x 16 rows, m16n8k8 single-tf32 -------------
    int ar = wy * 16 + qr;           // A rows: ar, ar+8
    const float* aR0 = &sA[ar * ALD];
    const float* aR1 = &sA[(ar + 8) * ALD];
    float dA[2][4] = { {0,0,0,0}, {0,0,0,0} };

#pragma unroll
    for (int kk = 0; kk < 16; kk++) {
        int k8 = kk * 8;
        unsigned a0 = f2tf32(aR0[k8 + qc]);
        unsigned a1 = f2tf32(aR1[k8 + qc]);
        unsigned a2 = f2tf32(aR0[k8 + qc + 4]);
        unsigned a3 = f2tf32(aR1[k8 + qc + 4]);

#pragma unroll
        for (int nt = 0; nt < 2; nt++) {
            int n = nt * 8 + qr;
            unsigned b0 = sBhi[n * ALD + k8 + qc];
            unsigned b1 = sBhi[n * ALD + k8 + qc + 4];
            mma_tf32(dA[nt][0], dA[nt][1], dA[nt][2], dA[nt][3],
                     a0, a1, a2, a3, b0, b1);
        }
    }

    // ---- epilogue: (D + alpha) * Ss -> out (operands pre-loaded) -----------
#pragma unroll
    for (int nt = 0; nt < 2; nt++) {
        int gc  = c0 + nt * 8 + 2 * qc;
        int rr0 = wy * 16 + qr;
        int rr1 = rr0 + 8;
        float2 o0 = make_float2((dA[nt][0] + alv[nt][0].x) * ssv[nt][0].x,
                                (dA[nt][1] + alv[nt][0].y) * ssv[nt][0].y);
        float2 o1 = make_float2((dA[nt][2] + alv[nt][1].x) * ssv[nt][1].x,
                                (dA[nt][3] + alv[nt][1].y) * ssv[nt][1].y);
        *reinterpret_cast<float2*>(&out[rr0 * Cc + gc]) = o0;
        *reinterpret_cast<float2*>(&out[rr1 * Cc + gc]) = o1;
    }
}

extern "C" void kernel_launch(void* const* d_in, const int* in_sizes, int n_in,
                              void* d_out, int out_size)
{
    const float* x    = (const float*)d_in[0];
    const float* Amat = (const float*)d_in[1];
    const float* taus = (const float*)d_in[2];
    const float* r0   = (const float*)d_in[3];
    float* out = (float*)d_out;

    (void)in_sizes; (void)n_in; (void)out_size;

    cudaFuncSetAttribute(fused_kernel, cudaFuncAttributeMaxDynamicSharedMemorySize,
                         SMEM_BYTES);

    fused_kernel<<<NB, 256, SMEM_BYTES>>>(x, Amat, taus, r0, out);
}

// round 14
// speedup vs baseline: 1.0030x; 1.0030x over previous
#include <cuda_runtime.h>

#define Nn   128
#define Hh   2
#define Ll   1024
#define Cc   (Hh * Ll)      /* 2048 columns = h*L flattened */
#define PRED (Nn * Cc)      /* 262144 */
#define NB   128            /* grid size (one wave, all co-resident) */

#define ALD  132            /* smem lead dim (conflict-free fragment reads) */
/* smem u32 words: sA_raw[128*ALD] sBhi[16*ALD] */
#define SMEM_U32   (144 * ALD)
#define SMEM_BYTES (SMEM_U32 * 4)   /* 76032 */

__device__ float    g_alpha[PRED];
__device__ float    g_Ss[PRED];
__device__ unsigned g_startctr;          /* monotonic run-ticket counter */
__device__ unsigned g_rowflag[128 * 8];  /* per-row monotonic done-counters (32B stride) */

// ---- helpers ---------------------------------------------------------------
__device__ __forceinline__ unsigned f2tf32(float f) {
    unsigned u;
    asm("cvt.rna.tf32.f32 %0, %1;" : "=r"(u) : "f"(f));
    return u;
}
__device__ __forceinline__ void mma_tf32(float& d0, float& d1, float& d2, float& d3,
                                         unsigned a0, unsigned a1, unsigned a2, unsigned a3,
                                         unsigned b0, unsigned b1) {
    asm("mma.sync.aligned.m16n8k8.row.col.f32.tf32.tf32.f32 "
        "{%0,%1,%2,%3}, {%4,%5,%6,%7}, {%8,%9}, {%0,%1,%2,%3};"
        : "+f"(d0), "+f"(d1), "+f"(d2), "+f"(d3)
        : "r"(a0), "r"(a1), "r"(a2), "r"(a3), "r"(b0), "r"(b1));
}
__device__ __forceinline__ void cp_async16(unsigned smem_addr, const void* gptr) {
    asm volatile("cp.async.cg.shared.global [%0], [%1], 16;"
                 :: "r"(smem_addr), "l"(gptr) : "memory");
}
__device__ __forceinline__ void row_release(int r) {
    asm volatile("red.release.gpu.add.u32 [%0], %1;"
                 :: "l"(&g_rowflag[r * 8]), "r"(1u) : "memory");
}
__device__ __forceinline__ void row_wait(int r, unsigned target) {
    unsigned v;
    const unsigned* p = &g_rowflag[r * 8];
    while (true) {
        asm volatile("ld.acquire.gpu.u32 %0, [%1];" : "=r"(v) : "l"(p));
        if (v >= target) break;
        __nanosleep(64);
    }
}

// ---------------------------------------------------------------------------
// Fused kernel: phase A scan (+A prefetch) -> per-row release -> phase B
// B-fill with per-row acquire-spin -> tensor-core GEMM + fused epilogue.
// Grid 128 x 256 threads. Block b: scan rows 2b,2b+1; GEMM cols b*16..+15.
// No full grid barrier: consumers overlap the scan tail of late rows.
// ---------------------------------------------------------------------------
__global__ void __launch_bounds__(256, 1) fused_kernel(const float* __restrict__ x,
                                                       const float* __restrict__ Amat,
                                                       const float* __restrict__ taus,
                                                       const float* __restrict__ r0dt,
                                                       float* __restrict__ out)
{
    extern __shared__ unsigned sm_u[];
    float*    sA   = reinterpret_cast<float*>(sm_u);      // [128][ALD] raw fp32 Amat
    unsigned* sBhi = sm_u + 128 * ALD;                    // [16][ALD]  ([n][k=m]) tf32
    __shared__ float wI[8], wC[8];
    __shared__ unsigned sGen;

    int tid = threadIdx.x;
    int b   = blockIdx.x;
    unsigned sbase = (unsigned)__cvta_generic_to_shared(sm_u);

    // run generation (monotonic, replay-safe): all NB tickets of one run share t/NB
    if (tid == 0) {
        unsigned t = atomicAdd(&g_startctr, 1u);
        sGen = t / NB + 1u;          // consumers wait rowflag >= sGen
    }

    // ---- A prefetch: full 128x128 Amat -> smem (overlaps entire phase A) ---
#pragma unroll
    for (int j = 0; j < 16; j++) {
        int i = j * 256 + tid;
        int r = i >> 5, cq = (i & 31) * 4;
        cp_async16(sbase + (unsigned)(r * ALD + cq) * 4, &Amat[r * 128 + cq]);
    }
    asm volatile("cp.async.commit_group;" ::: "memory");

    // ---- Phase A: scan rows 2b (threads 0-127) and 2b+1 (threads 128-255) --
    int half = tid >> 7;            // 0 or 1
    int t    = tid & 127;
    int row  = 2 * b + half;
    int lane = tid & 31;
    int wloc = (tid >> 5) & 3;      // warp index within this half
    int base = row * Ll + t * 8;

    const float4* xv = reinterpret_cast<const float4*>(x + base);
    float4 v0 = xv[0], v1 = xv[1];
    float s[8] = { fmaxf(v0.x, 0.f), fmaxf(v0.y, 0.f), fmaxf(v0.z, 0.f), fmaxf(v0.w, 0.f),
                   fmaxf(v1.x, 0.f), fmaxf(v1.y, 0.f), fmaxf(v1.z, 0.f), fmaxf(v1.w, 0.f) };

    // third output: tempAmat.T = Amat + I (block b handles row b)
    if (tid < 128) {
        float a = Amat[b * 128 + tid];
        out[2 * PRED + b * 128 + tid] = a + (b == tid ? 1.f : 0.f);
    }

    float tau = taus[row];
    float R0  = r0dt[row];
    float d   = 1.f - 1.f / tau;

    float cum = 0.f, isv = 0.f;
#pragma unroll
    for (int k = 0; k < 8; k++) { cum += s[k]; isv = fmaf(d, isv, s[k]); }

    float d2 = d * d, d4 = d2 * d2, r8 = d4 * d4;   // d^8

    float inclI = isv, inclC = cum, rp = r8;
#pragma unroll
    for (int off = 1; off < 32; off <<= 1) {
        float ui = __shfl_up_sync(0xffffffffu, inclI, off);
        float uc = __shfl_up_sync(0xffffffffu, inclC, off);
        if (lane >= off) { inclI = fmaf(rp, ui, inclI); inclC += uc; }
        rp *= rp;
    }

    if (lane == 31) { wI[half * 4 + wloc] = inclI; wC[half * 4 + wloc] = inclC; }
    __syncthreads();

    float Rw = rp;                                  // d^256
    float exI = 0.f, exC = 0.f, aI = 0.f, aC = 0.f;
#pragma unroll
    for (int w = 0; w < 4; w++) {
        if (w == wloc) { exI = aI; exC = aC; }
        aI = fmaf(Rw, aI, wI[half * 4 + w]);
        aC += wC[half * 4 + w];
    }

    float upI = __shfl_up_sync(0xffffffffu, inclI, 1);
    float upC = __shfl_up_sync(0xffffffffu, inclC, 1);
    if (lane == 0) { upI = 0.f; upC = 0.f; }
    float XI = fmaf(exI, __powf(r8, (float)lane), upI);
    float XC = upC + exC;

    float al[8], ss[8];
    float ci = XI, cc = XC;
#pragma unroll
    for (int k = 0; k < 8; k++) {
        ci = fmaf(d, ci, s[k]);
        cc += s[k];
        al[k] = 1.f - __expf(-R0 * ci);
        ss[k] = 1.f - cc;
    }

    float4* ga = reinterpret_cast<float4*>(g_alpha + base);
    ga[0] = make_float4(al[0], al[1], al[2], al[3]);
    ga[1] = make_float4(al[4], al[5], al[6], al[7]);
    float4* gs = reinterpret_cast<float4*>(g_Ss + base);
    gs[0] = make_float4(ss[0], ss[1], ss[2], ss[3]);
    gs[1] = make_float4(ss[4], ss[5], ss[6], ss[7]);
    float4* go = reinterpret_cast<float4*>(out + PRED + base);   // signal output
    go[0] = make_float4(s[0], s[1], s[2], s[3]);
    go[1] = make_float4(s[4], s[5], s[6], s[7]);

    // A must be in smem before phase B reads it
    asm volatile("cp.async.wait_group 0;" ::: "memory");
    __syncthreads();                 // all rows' stores issued block-wide
    if (tid == 0)   row_release(2 * b);
    if (tid == 128) row_release(2 * b + 1);

    // ---- Phase B: B-tile fill with per-row acquire (overlaps late producers)
    int c0 = b * 16;
    unsigned gen = sGen;
    {
        int m  = tid >> 1;
        int j0 = (tid & 1) * 8;
        row_wait(m, gen);
        const float4* src = reinterpret_cast<const float4*>(&g_alpha[m * Cc + c0 + j0]);
        float4 q0 = src[0], q1 = src[1];
        float v[8] = { q0.x, q0.y, q0.z, q0.w, q1.x, q1.y, q1.z, q1.w };
#pragma unroll
        for (int j = 0; j < 8; j++)
            sBhi[(j0 + j) * ALD + m] = f2tf32(v[j]);
    }
    __syncthreads();                 // all 128 rows acquired by the block

    // ---- Hoist epilogue operands (L2-hot) so the mainloop hides their latency
    int wy = tid >> 5;               // warp 0..7
    int qr = lane >> 2;              // 0..7
    int qc = lane & 3;               // 0..3
    float2 alv[2][2], ssv[2][2];
#pragma unroll
    for (int nt = 0; nt < 2; nt++) {
        int gc  = c0 + nt * 8 + 2 * qc;
        int rr0 = wy * 16 + qr;
        int rr1 = rr0 + 8;
        alv[nt][0] = *reinterpret_cast<const float2*>(&g_alpha[rr0 * Cc + gc]);
        ssv[nt][0] = *reinterpret_cast<const float2*>(&g_Ss[rr0 * Cc + gc]);
        alv[nt][1] = *reinterpret_cast<const float2*>(&g_alpha[rr1 * Cc + gc]);
        ssv[nt][1] = *reinterpret_cast<const float2*>(&g_Ss[rr1 * Cc + gc]);
    }

    // ---- GEMM mainloop: 8 warps x 16 rows, m16n8k8 single-tf32 -------------
    int ar = wy * 16 + qr;           // A rows: ar, ar+8
    const float* aR0 = &sA[ar * ALD];
    const float* aR1 = &sA[(ar + 8) * ALD];
    float dA[2][4] = { {0,0,0,0}, {0,0,0,0} };

#pragma unroll
    for (int kk = 0; kk < 16; kk++) {
        int k8 = kk * 8;
        unsigned a0 = f2tf32(aR0[k8 + qc]);
        unsigned a1 = f2tf32(aR1[k8 + qc]);
        unsigned a2 = f2tf32(aR0[k8 + qc + 4]);
        unsigned a3 = f2tf32(aR1[k8 + qc + 4]);

#pragma unroll
        for (int nt = 0; nt < 2; nt++) {
            int n = nt * 8 + qr;
            unsigned b0 = sBhi[n * ALD + k8 + qc];
            unsigned b1 = sBhi[n * ALD + k8 + qc + 4];
            mma_tf32(dA[nt][0], dA[nt][1], dA[nt][2], dA[nt][3],
                     a0, a1, a2, a3, b0, b1);
        }
    }

    // ---- epilogue: (D + alpha) * Ss -> out (operands pre-loaded) -----------
#pragma unroll
    for (int nt = 0; nt < 2; nt++) {
        int gc  = c0 + nt * 8 + 2 * qc;
        int rr0 = wy * 16 + qr;
        int rr1 = rr0 + 8;
        float2 o0 = make_float2((dA[nt][0] + alv[nt][0].x) * ssv[nt][0].x,
                                (dA[nt][1] + alv[nt][0].y) * ssv[nt][0].y);
        float2 o1 = make_float2((dA[nt][2] + alv[nt][1].x) * ssv[nt][1].x,
                                (dA[nt][3] + alv[nt][1].y) * ssv[nt][1].y);
        *reinterpret_cast<float2*>(&out[rr0 * Cc + gc]) = o0;
        *reinterpret_cast<float2*>(&out[rr1 * Cc + gc]) = o1;
    }
}

extern "C" void kernel_launch(void* const* d_in, const int* in_sizes, int n_in,
                              void* d_out, int out_size)
{
    const float* x    = (const float*)d_in[0];
    const float* Amat = (const float*)d_in[1];
    const float* taus = (const float*)d_in[2];
    const float* r0   = (const float*)d_in[3];
    float* out = (float*)d_out;

    (void)in_sizes; (void)n_in; (void)out_size;

    cudaFuncSetAttribute(fused_kernel, cudaFuncAttributeMaxDynamicSharedMemorySize,
                         SMEM_BYTES);

    fused_kernel<<<NB, 256, SMEM_BYTES>>>(x, Amat, taus, r0, out);
}